// round 2
// baseline (speedup 1.0000x reference)
#include <cuda_runtime.h>
#include <cuda_bf16.h>

#define NJ   24
#define FEAT 6
#define HID  7

// Identity order is topological: PARENTS[j] < j for all j>0.
__device__ __constant__ const int kParents_unused = 0; // (documentation only)

static __device__ __forceinline__ constexpr int PARENT(int j) {
    constexpr int P[NJ] = {-1,0,0,0,1,2,3,4,5,6,7,8,9,9,9,12,13,14,16,17,18,19,20,21};
    return P[j];
}

// Padded shared-memory layout (all rows padded to 8 floats for LDS.128):
//  W1: j*56 + r*8 + c          (1344 floats)   offset 0
//  b1: 1344 + j*8 + r          ( 192 floats)
//  W2: 1536 + j*48 + q*8 + c   (1152 floats)
//  b2: 2688 + j*8 + q          ( 192 floats)
#define SMEM_FLOATS 2880

__global__ __launch_bounds__(256, 2)
void se1d_kernel(const float* __restrict__ x,
                 const float* __restrict__ W1, const float* __restrict__ b1,
                 const float* __restrict__ W2, const float* __restrict__ b2,
                 float* __restrict__ out, int B)
{
    __shared__ float s[SMEM_FLOATS];
    const int tid = threadIdx.x;

    // Stage weights into padded smem (pad lanes zeroed for safety).
    for (int i = tid; i < SMEM_FLOATS; i += 256) s[i] = 0.f;
    __syncthreads();
    for (int i = tid; i < NJ * HID * HID; i += 256) {          // 1176
        int j = i / 49, rem = i % 49, r = rem / 7, c = rem % 7;
        s[j * 56 + r * 8 + c] = W1[i];
    }
    for (int i = tid; i < NJ * HID; i += 256) {                // 168
        int j = i / 7, r = i % 7;
        s[1344 + j * 8 + r] = b1[i];
    }
    for (int i = tid; i < NJ * FEAT * HID; i += 256) {         // 1008
        int j = i / 42, rem = i % 42, q = rem / 7, c = rem % 7;
        s[1536 + j * 48 + q * 8 + c] = W2[i];
    }
    for (int i = tid; i < NJ * FEAT; i += 256) {               // 144
        int j = i / 6, q = i % 6;
        s[2688 + j * 8 + q] = b2[i];
    }
    __syncthreads();

    const int b = blockIdx.x * 256 + tid;
    if (b >= B) return;

    // Load this sample's x row: 24 floats = 6 float4 (b*96 bytes, 16B aligned).
    float xr[NJ];
    const float4* xv = reinterpret_cast<const float4*>(x + (size_t)b * NJ);
    #pragma unroll
    for (int k = 0; k < 6; k++) {
        float4 v = __ldcs(xv + k);
        xr[4 * k + 0] = v.x; xr[4 * k + 1] = v.y;
        xr[4 * k + 2] = v.z; xr[4 * k + 3] = v.w;
    }

    float feat[NJ][FEAT];   // compile-time indexed only -> registers
    float* o = out + (size_t)b * (NJ * FEAT);
    const float4* s4 = reinterpret_cast<const float4*>(s);

    #pragma unroll
    for (int j = 0; j < NJ; j++) {
        const int p = PARENT(j);

        float inp[HID];
        inp[0] = xr[j];
        if (p < 0) {
            #pragma unroll
            for (int f = 0; f < FEAT; f++) inp[1 + f] = 0.f;
        } else {
            #pragma unroll
            for (int f = 0; f < FEAT; f++) inp[1 + f] = feat[p][f];
        }

        // Layer 1: h = relu(W1[j] @ inp + b1[j])
        float4 bb0 = s4[(1344 + j * 8) / 4];
        float4 bb1 = s4[(1344 + j * 8) / 4 + 1];
        const float bv[8] = {bb0.x, bb0.y, bb0.z, bb0.w, bb1.x, bb1.y, bb1.z, bb1.w};
        float h[HID];
        #pragma unroll
        for (int r = 0; r < HID; r++) {
            float4 w0 = s4[(j * 56 + r * 8) / 4];
            float4 w1 = s4[(j * 56 + r * 8) / 4 + 1];
            float acc = bv[r];
            acc = fmaf(w0.x, inp[0], acc);
            acc = fmaf(w0.y, inp[1], acc);
            acc = fmaf(w0.z, inp[2], acc);
            acc = fmaf(w0.w, inp[3], acc);
            acc = fmaf(w1.x, inp[4], acc);
            acc = fmaf(w1.y, inp[5], acc);
            acc = fmaf(w1.z, inp[6], acc);
            h[r] = fmaxf(acc, 0.f);
        }

        // Layer 2: feat[j] = relu(W2[j] @ h + b2[j])
        float4 cb0 = s4[(2688 + j * 8) / 4];
        float4 cb1 = s4[(2688 + j * 8) / 4 + 1];
        const float cv[8] = {cb0.x, cb0.y, cb0.z, cb0.w, cb1.x, cb1.y, cb1.z, cb1.w};
        #pragma unroll
        for (int q = 0; q < FEAT; q++) {
            float4 w0 = s4[(1536 + j * 48 + q * 8) / 4];
            float4 w1 = s4[(1536 + j * 48 + q * 8) / 4 + 1];
            float acc = cv[q];
            acc = fmaf(w0.x, h[0], acc);
            acc = fmaf(w0.y, h[1], acc);
            acc = fmaf(w0.z, h[2], acc);
            acc = fmaf(w0.w, h[3], acc);
            acc = fmaf(w1.x, h[4], acc);
            acc = fmaf(w1.y, h[5], acc);
            acc = fmaf(w1.z, h[6], acc);
            feat[j][q] = fmaxf(acc, 0.f);
        }

        // Stream this joint's 6 outputs (offset j*24 bytes: 8B aligned -> float2).
        float2* ov = reinterpret_cast<float2*>(o + j * FEAT);
        __stcs(ov + 0, make_float2(feat[j][0], feat[j][1]));
        __stcs(ov + 1, make_float2(feat[j][2], feat[j][3]));
        __stcs(ov + 2, make_float2(feat[j][4], feat[j][5]));
    }
}

extern "C" void kernel_launch(void* const* d_in, const int* in_sizes, int n_in,
                              void* d_out, int out_size)
{
    const float* x  = (const float*)d_in[0];
    const float* W1 = (const float*)d_in[1];
    const float* b1 = (const float*)d_in[2];
    const float* W2 = (const float*)d_in[3];
    const float* b2 = (const float*)d_in[4];
    float* out = (float*)d_out;

    const int B = in_sizes[0] / NJ;
    const int grid = (B + 255) / 256;
    se1d_kernel<<<grid, 256>>>(x, W1, b1, W2, b2, out, B);
}